// round 8
// baseline (speedup 1.0000x reference)
#include <cuda_runtime.h>
#include <math.h>
#include <stdint.h>

// Problem constants
#define BB   8
#define SEQ  1024
#define DIM  768
#define NH   12
#define KG   4
#define HD   64
#define MTOT (BB*SEQ)     // 8192

// Scratch (static device globals — no runtime allocation allowed)
// g_qk / g_v hold TF32 bit patterns (converted in GEMM epilogue).
__device__ float g_qk[(size_t)MTOT * 512];   // per row: [0,256)=q heads, [256,512)=k heads
__device__ float g_v [(size_t)MTOT * DIM];
__device__ float g_ctx[(size_t)MTOT * DIM];
__device__ float g_gl[(size_t)BB * KG * SEQ * SEQ];   // raw global logits q_k . k_k^T

// ---------------------------------------------------------------------------
// TF32 / cp.async helpers
// ---------------------------------------------------------------------------
__device__ __forceinline__ uint32_t f2tf(float x) {
    uint32_t r;
    asm("cvt.rna.tf32.f32 %0, %1;" : "=r"(r) : "f"(x));
    return r;
}

__device__ __forceinline__ void mma_tf32(float* d, const uint32_t* a, const uint32_t* b) {
    asm volatile(
        "mma.sync.aligned.m16n8k8.row.col.f32.tf32.tf32.f32 "
        "{%0,%1,%2,%3}, {%4,%5,%6,%7}, {%8,%9}, {%0,%1,%2,%3};"
        : "+f"(d[0]), "+f"(d[1]), "+f"(d[2]), "+f"(d[3])
        : "r"(a[0]), "r"(a[1]), "r"(a[2]), "r"(a[3]), "r"(b[0]), "r"(b[1]));
}

__device__ __forceinline__ void cp16(uint32_t smem_dst, const void* gsrc) {
    asm volatile("cp.async.cg.shared.global [%0], [%1], 16;"
                 :: "r"(smem_dst), "l"(gsrc));
}
__device__ __forceinline__ void cp_commit() {
    asm volatile("cp.async.commit_group;");
}
__device__ __forceinline__ void cp_wait_all() {
    asm volatile("cp.async.wait_group 0;");
}
__device__ __forceinline__ void bar_named(int id, int nthreads) {
    asm volatile("bar.sync %0, %1;" :: "r"(id), "r"(nthreads) : "memory");
}

// ---------------------------------------------------------------------------
// TF32 tensor-core GEMM: C[M, NC] = A[M, 768] @ W[NC, 768]^T (+ bias).
// ---------------------------------------------------------------------------
#define GS_STR 36

template<int NC, bool OUT_TF32, bool BIAS>
__global__ void __launch_bounds__(256, 2) tf32_gemm_nt(const float* __restrict__ A,
                                                       const float* __restrict__ W,
                                                       const float* __restrict__ bias,
                                                       float* __restrict__ C)
{
    __shared__ uint32_t As[128 * GS_STR];
    __shared__ uint32_t Ws[128 * GS_STR];

    const int m0  = blockIdx.y * 128;
    const int n0  = blockIdx.x * 128;
    const int tid = threadIdx.x;
    const int lane = tid & 31;
    const int warp = tid >> 5;
    const int warp_m = warp >> 2;
    const int warp_n = warp & 3;
    const int qd = lane >> 2;
    const int qq = lane & 3;

    const int lr = tid >> 1;
    const int lc = (tid & 1) * 16;

    const float* Ap = A + (size_t)(m0 + lr) * DIM + lc;
    const float* Wp = W + (size_t)(n0 + lr) * DIM + lc;
    uint32_t* Asd = &As[lr * GS_STR + lc];
    uint32_t* Wsd = &Ws[lr * GS_STR + lc];

    float acc[4][4][4];
#pragma unroll
    for (int mf = 0; mf < 4; mf++)
#pragma unroll
        for (int nf = 0; nf < 4; nf++)
#pragma unroll
            for (int c = 0; c < 4; c++) acc[mf][nf][c] = 0.f;

    float4 av[4], wv[4];
#pragma unroll
    for (int i = 0; i < 4; i++) {
        av[i] = *(const float4*)(Ap + i * 4);
        wv[i] = *(const float4*)(Wp + i * 4);
    }

    for (int k0 = 0; k0 < DIM; k0 += 32) {
        __syncthreads();
#pragma unroll
        for (int i = 0; i < 4; i++) {
            uint4 at, wt;
            at.x = f2tf(av[i].x); at.y = f2tf(av[i].y);
            at.z = f2tf(av[i].z); at.w = f2tf(av[i].w);
            wt.x = f2tf(wv[i].x); wt.y = f2tf(wv[i].y);
            wt.z = f2tf(wv[i].z); wt.w = f2tf(wv[i].w);
            *(uint4*)(Asd + i * 4) = at;
            *(uint4*)(Wsd + i * 4) = wt;
        }
        __syncthreads();

        if (k0 + 32 < DIM) {
#pragma unroll
            for (int i = 0; i < 4; i++) {
                av[i] = *(const float4*)(Ap + k0 + 32 + i * 4);
                wv[i] = *(const float4*)(Wp + k0 + 32 + i * 4);
            }
        }

#pragma unroll
        for (int kk = 0; kk < 32; kk += 8) {
            uint32_t a[4][4];
#pragma unroll
            for (int mf = 0; mf < 4; mf++) {
                const int base = warp_m * 64 + mf * 16 + qd;
                a[mf][0] = As[base * GS_STR + kk + qq];
                a[mf][1] = As[(base + 8) * GS_STR + kk + qq];
                a[mf][2] = As[base * GS_STR + kk + qq + 4];
                a[mf][3] = As[(base + 8) * GS_STR + kk + qq + 4];
            }
#pragma unroll
            for (int nf = 0; nf < 4; nf++) {
                const int col = warp_n * 32 + nf * 8 + qd;
                uint32_t bfr[2];
                bfr[0] = Ws[col * GS_STR + kk + qq];
                bfr[1] = Ws[col * GS_STR + kk + qq + 4];
#pragma unroll
                for (int mf = 0; mf < 4; mf++)
                    mma_tf32(acc[mf][nf], a[mf], bfr);
            }
        }
    }

#pragma unroll
    for (int mf = 0; mf < 4; mf++) {
        const int row0 = m0 + warp_m * 64 + mf * 16 + qd;
        const int row1 = row0 + 8;
#pragma unroll
        for (int nf = 0; nf < 4; nf++) {
            const int col = n0 + warp_n * 32 + nf * 8 + 2 * qq;
            float2 o0, o1;
            o0.x = acc[mf][nf][0]; o0.y = acc[mf][nf][1];
            o1.x = acc[mf][nf][2]; o1.y = acc[mf][nf][3];
            if (BIAS) {
                const float2 bv = *(const float2*)&bias[col];
                o0.x += bv.x; o0.y += bv.y;
                o1.x += bv.x; o1.y += bv.y;
            }
            if (OUT_TF32) {
                o0.x = __uint_as_float(f2tf(o0.x)); o0.y = __uint_as_float(f2tf(o0.y));
                o1.x = __uint_as_float(f2tf(o1.x)); o1.y = __uint_as_float(f2tf(o1.y));
            }
            *(float2*)&C[(size_t)row0 * NC + col] = o0;
            *(float2*)&C[(size_t)row1 * NC + col] = o1;
        }
    }
}

// ---------------------------------------------------------------------------
// Kernel A: global logits. For (b, kh): gl[i,j] = q_kh[i] . k_kh[j], K=64.
// ---------------------------------------------------------------------------
__global__ void __launch_bounds__(256, 2) gl_gemm(const float* __restrict__ QK,
                                                  float* __restrict__ GL)
{
    __shared__ uint32_t As[128 * GS_STR];
    __shared__ uint32_t Ws[128 * GS_STR];

    const int b  = blockIdx.z >> 2;
    const int kh = blockIdx.z & 3;
    const int m0 = blockIdx.y * 128;
    const int n0 = blockIdx.x * 128;
    const int tid = threadIdx.x;
    const int lane = tid & 31;
    const int warp = tid >> 5;
    const int warp_m = warp >> 2;
    const int warp_n = warp & 3;
    const int qd = lane >> 2;
    const int qq = lane & 3;

    const int lr = tid >> 1;
    const int lc = (tid & 1) * 16;

    const uint32_t* Ap = (const uint32_t*)QK + (size_t)(b * SEQ + m0 + lr) * 512 + kh * HD + lc;
    const uint32_t* Wp = (const uint32_t*)QK + (size_t)(b * SEQ + n0 + lr) * 512 + 256 + kh * HD + lc;
    uint32_t* Asd = &As[lr * GS_STR + lc];
    uint32_t* Wsd = &Ws[lr * GS_STR + lc];

    float acc[4][4][4];
#pragma unroll
    for (int mf = 0; mf < 4; mf++)
#pragma unroll
        for (int nf = 0; nf < 4; nf++)
#pragma unroll
            for (int c = 0; c < 4; c++) acc[mf][nf][c] = 0.f;

    uint4 av[4], wv[4];
#pragma unroll
    for (int i = 0; i < 4; i++) {
        av[i] = *(const uint4*)(Ap + i * 4);
        wv[i] = *(const uint4*)(Wp + i * 4);
    }

#pragma unroll
    for (int k0 = 0; k0 < HD; k0 += 32) {
        __syncthreads();
#pragma unroll
        for (int i = 0; i < 4; i++) {
            *(uint4*)(Asd + i * 4) = av[i];
            *(uint4*)(Wsd + i * 4) = wv[i];
        }
        __syncthreads();

        if (k0 + 32 < HD) {
#pragma unroll
            for (int i = 0; i < 4; i++) {
                av[i] = *(const uint4*)(Ap + k0 + 32 + i * 4);
                wv[i] = *(const uint4*)(Wp + k0 + 32 + i * 4);
            }
        }

#pragma unroll
        for (int kk = 0; kk < 32; kk += 8) {
            uint32_t a[4][4];
#pragma unroll
            for (int mf = 0; mf < 4; mf++) {
                const int base = warp_m * 64 + mf * 16 + qd;
                a[mf][0] = As[base * GS_STR + kk + qq];
                a[mf][1] = As[(base + 8) * GS_STR + kk + qq];
                a[mf][2] = As[base * GS_STR + kk + qq + 4];
                a[mf][3] = As[(base + 8) * GS_STR + kk + qq + 4];
            }
#pragma unroll
            for (int nf = 0; nf < 4; nf++) {
                const int col = warp_n * 32 + nf * 8 + qd;
                uint32_t bfr[2];
                bfr[0] = Ws[col * GS_STR + kk + qq];
                bfr[1] = Ws[col * GS_STR + kk + qq + 4];
#pragma unroll
                for (int mf = 0; mf < 4; mf++)
                    mma_tf32(acc[mf][nf], a[mf], bfr);
            }
        }
    }

    float* Cp = GL + (size_t)blockIdx.z * SEQ * SEQ;
#pragma unroll
    for (int mf = 0; mf < 4; mf++) {
        const int row0 = m0 + warp_m * 64 + mf * 16 + qd;
        const int row1 = row0 + 8;
#pragma unroll
        for (int nf = 0; nf < 4; nf++) {
            const int col = n0 + warp_n * 32 + nf * 8 + 2 * qq;
            float2 o0, o1;
            o0.x = acc[mf][nf][0]; o0.y = acc[mf][nf][1];
            o1.x = acc[mf][nf][2]; o1.y = acc[mf][nf][3];
            *(float2*)&Cp[(size_t)row0 * SEQ + col] = o0;
            *(float2*)&Cp[(size_t)row1 * SEQ + col] = o1;
        }
    }
}

// ---------------------------------------------------------------------------
// Kernel B: mix + softmax + AV. THREE heads per CTA (768 threads, 24 warps).
// Sg read DIRECTLY from global at fragment positions (no smem staging, no
// Sg barrier). V double-buffered via cp.async per head. Per-head named
// barriers (256 threads) fully decouple the three heads.
// ---------------------------------------------------------------------------
#define HPC  3     // heads per CTA
#define VS_STR 72
#define PS_STR 68
#define GLK ((size_t)SEQ * SEQ)   // k-head stride in g_gl (floats)

__global__ void __launch_bounds__(768) fish_mix_attn(const float* __restrict__ mixl,
                                                     const float* __restrict__ GL,
                                                     float* __restrict__ ctx)
{
    extern __shared__ float sm[];
    float* VsAll = sm;                            // [3][2][64*VS_STR]
    float* PsAll = VsAll + HPC * 2 * 64 * VS_STR; // [3][64*PS_STR]
    float* sMaxA = PsAll + HPC * 64 * PS_STR;     // [3][128]
    float* sSumA = sMaxA + HPC * 128;             // [3][128]

    const int i0   = blockIdx.x * 64;
    const int b    = blockIdx.z;
    const int tid  = threadIdx.x;
    const int hh   = tid >> 8;                    // 0..2 head slot
    const int t    = tid & 255;
    const int h    = blockIdx.y * HPC + hh;
    const int lane = tid & 31;
    const int warp8 = t >> 5;                     // warp within head
    const int mstrip = warp8 >> 1;
    const int nhalf  = warp8 & 1;
    const int qd = lane >> 2;
    const int qq = lane & 3;
    const int bar_id = hh + 1;                    // named barrier per head

    const int row0 = 16 * mstrip + qd;
    const int row1 = row0 + 8;

    float* Vs0  = VsAll + hh * 2 * 64 * VS_STR;
    float* Vs1  = Vs0 + 64 * VS_STR;
    float* Ps   = PsAll + hh * 64 * PS_STR;
    float* sMax = sMaxA + hh * 128;
    float* sSum = sSumA + hh * 128;

    // V copy slots (per head: 256 threads, 16 col-chunks x 16 rows, 4 rows ea)
    const int vc = (t & 15) * 4;
    const int vr = t >> 4;                        // 0..15
    const uint32_t VsA0 = (uint32_t)__cvta_generic_to_shared(Vs0);
    const uint32_t VsA1 = (uint32_t)__cvta_generic_to_shared(Vs1);

    // Prologue: async-copy V(0)
#pragma unroll
    for (int i = 0; i < 4; i++) {
        const int r = vr + i * 16;
        cp16(VsA0 + (uint32_t)(r * VS_STR + vc) * 4,
             &g_v[((size_t)(b * SEQ + 0 + r)) * DIM + h * HD + vc]);
    }
    cp_commit();

    // mixw = softmax(mix_logits[h,:]) * HEAD_DIM^-0.5
    float ml0 = mixl[h * KG + 0], ml1 = mixl[h * KG + 1];
    float ml2 = mixl[h * KG + 2], ml3 = mixl[h * KG + 3];
    float mm = fmaxf(fmaxf(ml0, ml1), fmaxf(ml2, ml3));
    float e0 = expf(ml0 - mm), e1 = expf(ml1 - mm);
    float e2 = expf(ml2 - mm), e3 = expf(ml3 - mm);
    float inv_es = 0.125f / (e0 + e1 + e2 + e3);
    const float mw0 = e0 * inv_es, mw1 = e1 * inv_es;
    const float mw2 = e2 * inv_es, mw3 = e3 * inv_es;

    float O[4][4];
#pragma unroll
    for (int nt = 0; nt < 4; nt++)
#pragma unroll
        for (int c = 0; c < 4; c++) O[nt][c] = 0.f;
    float m_0 = -INFINITY, m_1 = -INFINITY, l_0 = 0.f, l_1 = 0.f;

    const uint32_t* Psu = (const uint32_t*)Ps;
    const uint32_t* pa0 = Psu + row0 * PS_STR + qq;
    const uint32_t* pa1 = Psu + row1 * PS_STR + qq;

    // Sg base pointer for this thread: k=0, row0, this warp's column strip
    const float* gb0 = GL + ((size_t)(b * KG) * SEQ + (i0 + row0)) * SEQ
                          + 32 * nhalf + 2 * qq;

    for (int j0 = 0; j0 < SEQ; j0 += 64) {
        const int vbuf = (j0 >> 6) & 1;
        const uint32_t* Vsu = (const uint32_t*)(vbuf ? Vs1 : Vs0);
        const bool more = (j0 + 64 < SEQ);

        cp_wait_all();                 // this thread's V(j) chunks landed
        bar_named(bar_id, 256);        // whole head sees V(j); AV(j-1) reads done

        // Prefetch V(j+1) into the other buffer
        if (more) {
            const uint32_t dstA = vbuf ? VsA0 : VsA1;
#pragma unroll
            for (int i = 0; i < 4; i++) {
                const int r = vr + i * 16;
                cp16(dstA + (uint32_t)(r * VS_STR + vc) * 4,
                     &g_v[((size_t)(b * SEQ + j0 + 64 + r)) * DIM + h * HD + vc]);
            }
            cp_commit();
        }

        // ---- S = sum_k mixw[k] * Sg_k  (direct LDG.64 from g_gl) ----
        float S[4][4];
        const float* gb = gb0 + j0;
#pragma unroll
        for (int nt = 0; nt < 4; nt++) {
            const float* p = gb + nt * 8;
            float2 a0 = *(const float2*)(p);
            float2 a1 = *(const float2*)(p + 8 * SEQ);
            float2 b0 = *(const float2*)(p + GLK);
            float2 b1 = *(const float2*)(p + GLK + 8 * SEQ);
            float2 c0 = *(const float2*)(p + 2 * GLK);
            float2 c1 = *(const float2*)(p + 2 * GLK + 8 * SEQ);
            float2 d0 = *(const float2*)(p + 3 * GLK);
            float2 d1 = *(const float2*)(p + 3 * GLK + 8 * SEQ);
            S[nt][0] = mw0 * a0.x + mw1 * b0.x + mw2 * c0.x + mw3 * d0.x;
            S[nt][1] = mw0 * a0.y + mw1 * b0.y + mw2 * c0.y + mw3 * d0.y;
            S[nt][2] = mw0 * a1.x + mw1 * b1.x + mw2 * c1.x + mw3 * d1.x;
            S[nt][3] = mw0 * a1.y + mw1 * b1.y + mw2 * c1.y + mw3 * d1.y;
        }

        // ---- online softmax (per head; cross-nhalf via smem + named bar) ----
        float mx0 = fmaxf(S[0][0], S[0][1]), mx1 = fmaxf(S[0][2], S[0][3]);
#pragma unroll
        for (int nt = 1; nt < 4; nt++) {
            mx0 = fmaxf(mx0, fmaxf(S[nt][0], S[nt][1]));
            mx1 = fmaxf(mx1, fmaxf(S[nt][2], S[nt][3]));
        }
        mx0 = fmaxf(mx0, __shfl_xor_sync(0xffffffffu, mx0, 1));
        mx0 = fmaxf(mx0, __shfl_xor_sync(0xffffffffu, mx0, 2));
        mx1 = fmaxf(mx1, __shfl_xor_sync(0xffffffffu, mx1, 1));
        mx1 = fmaxf(mx1, __shfl_xor_sync(0xffffffffu, mx1, 2));
        if (qq == 0) {
            sMax[row0 * 2 + nhalf] = mx0;
            sMax[row1 * 2 + nhalf] = mx1;
        }
        bar_named(bar_id, 256);

        const float tm0 = fmaxf(sMax[row0 * 2], sMax[row0 * 2 + 1]);
        const float tm1 = fmaxf(sMax[row1 * 2], sMax[row1 * 2 + 1]);
        const float mn0 = fmaxf(m_0, tm0), mn1 = fmaxf(m_1, tm1);
        const float corr0 = __expf(m_0 - mn0), corr1 = __expf(m_1 - mn1);
        m_0 = mn0; m_1 = mn1;

        float rs0 = 0.f, rs1 = 0.f;
#pragma unroll
        for (int nt = 0; nt < 4; nt++) {
            const float p0 = __expf(S[nt][0] - mn0);
            const float p1 = __expf(S[nt][1] - mn0);
            const float p2 = __expf(S[nt][2] - mn1);
            const float p3 = __expf(S[nt][3] - mn1);
            rs0 += p0 + p1; rs1 += p2 + p3;
            const int col = 32 * nhalf + nt * 8 + 2 * qq;
            uint2 w0, w1;
            w0.x = f2tf(p0); w0.y = f2tf(p1);
            w1.x = f2tf(p2); w1.y = f2tf(p3);
            *(uint2*)&Ps[row0 * PS_STR + col] = w0;
            *(uint2*)&Ps[row1 * PS_STR + col] = w1;
            O[nt][0] *= corr0; O[nt][1] *= corr0;
            O[nt][2] *= corr1; O[nt][3] *= corr1;
        }
        rs0 += __shfl_xor_sync(0xffffffffu, rs0, 1);
        rs0 += __shfl_xor_sync(0xffffffffu, rs0, 2);
        rs1 += __shfl_xor_sync(0xffffffffu, rs1, 1);
        rs1 += __shfl_xor_sync(0xffffffffu, rs1, 2);
        if (qq == 0) {
            sSum[row0 * 2 + nhalf] = rs0;
            sSum[row1 * 2 + nhalf] = rs1;
        }
        bar_named(bar_id, 256);        // Ps complete + sSum written
        l_0 = l_0 * corr0 + sSum[row0 * 2] + sSum[row0 * 2 + 1];
        l_1 = l_1 * corr1 + sSum[row1 * 2] + sSum[row1 * 2 + 1];

        // ---- O += P V ----
#pragma unroll
        for (int k0 = 0; k0 < 64; k0 += 8) {
            uint32_t a[4];
            a[0] = pa0[k0]; a[1] = pa1[k0];
            a[2] = pa0[k0 + 4]; a[3] = pa1[k0 + 4];
#pragma unroll
            for (int nt = 0; nt < 4; nt++) {
                const int d = 32 * nhalf + nt * 8 + qd;
                uint32_t bf[2];
                bf[0] = Vsu[(k0 + qq) * VS_STR + d];
                bf[1] = Vsu[(k0 + qq + 4) * VS_STR + d];
                mma_tf32(O[nt], a, bf);
            }
        }
    }

    // Epilogue: normalize, write ctx (B,N,768) fp32
    const float inv0 = 1.f / l_0, inv1 = 1.f / l_1;
    const size_t r0off = ((size_t)(b * SEQ + i0 + row0)) * DIM + h * HD;
    const size_t r1off = ((size_t)(b * SEQ + i0 + row1)) * DIM + h * HD;
#pragma unroll
    for (int nt = 0; nt < 4; nt++) {
        const int col = 32 * nhalf + nt * 8 + 2 * qq;
        float2 o0; o0.x = O[nt][0] * inv0; o0.y = O[nt][1] * inv0;
        float2 o1; o1.x = O[nt][2] * inv1; o1.y = O[nt][3] * inv1;
        *(float2*)&ctx[r0off + col] = o0;
        *(float2*)&ctx[r1off + col] = o1;
    }
}

// ---------------------------------------------------------------------------
// Launch
// ---------------------------------------------------------------------------
extern "C" void kernel_launch(void* const* d_in, const int* in_sizes, int n_in,
                              void* d_out, int out_size)
{
    const float* x      = (const float*)d_in[0];
    const float* w_qkv  = (const float*)d_in[1];
    const float* mixl   = (const float*)d_in[2];
    const float* w_v    = (const float*)d_in[3];
    const float* w_proj = (const float*)d_in[4];
    const float* b_proj = (const float*)d_in[5];
    float* out = (float*)d_out;

    float *qk, *v, *ctx, *gl;
    cudaGetSymbolAddress((void**)&qk,  g_qk);
    cudaGetSymbolAddress((void**)&v,   g_v);
    cudaGetSymbolAddress((void**)&ctx, g_ctx);
    cudaGetSymbolAddress((void**)&gl,  g_gl);

    const int attn_smem = (HPC * 2 * 64 * VS_STR + HPC * 64 * PS_STR + HPC * 256)
                          * (int)sizeof(float);
    cudaFuncSetAttribute(fish_mix_attn, cudaFuncAttributeMaxDynamicSharedMemorySize, attn_smem);

    // 1) qk = x @ w_qkv[0:512]^T  -> tf32 bits
    tf32_gemm_nt<512, true, false><<<dim3(4, 64), 256>>>(x, w_qkv, nullptr, qk);
    // 2) v = x @ w_v^T            -> tf32 bits
    tf32_gemm_nt<768, true, false><<<dim3(6, 64), 256>>>(x, w_v, nullptr, v);
    // A) global logits per (b, k-head): gl = q_k . k_k^T  (fp32 raw)
    gl_gemm<<<dim3(8, 8, BB * KG), 256>>>(qk, gl);
    // B) mix + softmax + AV, 3 heads per CTA, direct-LDG Sg
    fish_mix_attn<<<dim3(SEQ / 64, NH / HPC, BB), HPC * 256, attn_smem>>>(mixl, gl, ctx);
    // 4) out = ctx @ w_proj^T + b_proj (fp32 out)
    tf32_gemm_nt<768, false, true><<<dim3(6, 64), 256>>>(ctx, w_proj, b_proj, out);
}

// round 9
// speedup vs baseline: 1.1232x; 1.1232x over previous
#include <cuda_runtime.h>
#include <math.h>
#include <stdint.h>

// Problem constants
#define BB   8
#define SEQ  1024
#define DIM  768
#define NH   12
#define KG   4
#define HD   64
#define MTOT (BB*SEQ)     // 8192

// Scratch (static device globals — no runtime allocation allowed)
// g_qk / g_v hold TF32 bit patterns (converted in GEMM epilogue).
__device__ float g_qk[(size_t)MTOT * 512];   // per row: [0,256)=q heads, [256,512)=k heads
__device__ float g_v [(size_t)MTOT * DIM];
__device__ float g_ctx[(size_t)MTOT * DIM];
__device__ float g_gl[(size_t)BB * KG * SEQ * SEQ];   // raw global logits q_k . k_k^T

// ---------------------------------------------------------------------------
// TF32 / cp.async helpers
// ---------------------------------------------------------------------------
__device__ __forceinline__ uint32_t f2tf(float x) {
    uint32_t r;
    asm("cvt.rna.tf32.f32 %0, %1;" : "=r"(r) : "f"(x));
    return r;
}

__device__ __forceinline__ void mma_tf32(float* d, const uint32_t* a, const uint32_t* b) {
    asm volatile(
        "mma.sync.aligned.m16n8k8.row.col.f32.tf32.tf32.f32 "
        "{%0,%1,%2,%3}, {%4,%5,%6,%7}, {%8,%9}, {%0,%1,%2,%3};"
        : "+f"(d[0]), "+f"(d[1]), "+f"(d[2]), "+f"(d[3])
        : "r"(a[0]), "r"(a[1]), "r"(a[2]), "r"(a[3]), "r"(b[0]), "r"(b[1]));
}

__device__ __forceinline__ void cp16(uint32_t smem_dst, const void* gsrc) {
    asm volatile("cp.async.cg.shared.global [%0], [%1], 16;"
                 :: "r"(smem_dst), "l"(gsrc));
}
__device__ __forceinline__ void cp_commit() {
    asm volatile("cp.async.commit_group;");
}
__device__ __forceinline__ void cp_wait_all() {
    asm volatile("cp.async.wait_group 0;");
}
__device__ __forceinline__ void cp_wait1() {
    asm volatile("cp.async.wait_group 1;");
}
__device__ __forceinline__ void bar_named(int id, int nthreads) {
    asm volatile("bar.sync %0, %1;" :: "r"(id), "r"(nthreads) : "memory");
}

// ---------------------------------------------------------------------------
// TF32 tensor-core GEMM: C[M, NC] = A[M, 768] @ W[NC, 768]^T (+ bias).
// ---------------------------------------------------------------------------
#define GS_STR 36

template<int NC, bool OUT_TF32, bool BIAS>
__global__ void __launch_bounds__(256, 2) tf32_gemm_nt(const float* __restrict__ A,
                                                       const float* __restrict__ W,
                                                       const float* __restrict__ bias,
                                                       float* __restrict__ C)
{
    __shared__ uint32_t As[128 * GS_STR];
    __shared__ uint32_t Ws[128 * GS_STR];

    const int m0  = blockIdx.y * 128;
    const int n0  = blockIdx.x * 128;
    const int tid = threadIdx.x;
    const int lane = tid & 31;
    const int warp = tid >> 5;
    const int warp_m = warp >> 2;
    const int warp_n = warp & 3;
    const int qd = lane >> 2;
    const int qq = lane & 3;

    const int lr = tid >> 1;
    const int lc = (tid & 1) * 16;

    const float* Ap = A + (size_t)(m0 + lr) * DIM + lc;
    const float* Wp = W + (size_t)(n0 + lr) * DIM + lc;
    uint32_t* Asd = &As[lr * GS_STR + lc];
    uint32_t* Wsd = &Ws[lr * GS_STR + lc];

    float acc[4][4][4];
#pragma unroll
    for (int mf = 0; mf < 4; mf++)
#pragma unroll
        for (int nf = 0; nf < 4; nf++)
#pragma unroll
            for (int c = 0; c < 4; c++) acc[mf][nf][c] = 0.f;

    float4 av[4], wv[4];
#pragma unroll
    for (int i = 0; i < 4; i++) {
        av[i] = *(const float4*)(Ap + i * 4);
        wv[i] = *(const float4*)(Wp + i * 4);
    }

    for (int k0 = 0; k0 < DIM; k0 += 32) {
        __syncthreads();
#pragma unroll
        for (int i = 0; i < 4; i++) {
            uint4 at, wt;
            at.x = f2tf(av[i].x); at.y = f2tf(av[i].y);
            at.z = f2tf(av[i].z); at.w = f2tf(av[i].w);
            wt.x = f2tf(wv[i].x); wt.y = f2tf(wv[i].y);
            wt.z = f2tf(wv[i].z); wt.w = f2tf(wv[i].w);
            *(uint4*)(Asd + i * 4) = at;
            *(uint4*)(Wsd + i * 4) = wt;
        }
        __syncthreads();

        if (k0 + 32 < DIM) {
#pragma unroll
            for (int i = 0; i < 4; i++) {
                av[i] = *(const float4*)(Ap + k0 + 32 + i * 4);
                wv[i] = *(const float4*)(Wp + k0 + 32 + i * 4);
            }
        }

#pragma unroll
        for (int kk = 0; kk < 32; kk += 8) {
            uint32_t a[4][4];
#pragma unroll
            for (int mf = 0; mf < 4; mf++) {
                const int base = warp_m * 64 + mf * 16 + qd;
                a[mf][0] = As[base * GS_STR + kk + qq];
                a[mf][1] = As[(base + 8) * GS_STR + kk + qq];
                a[mf][2] = As[base * GS_STR + kk + qq + 4];
                a[mf][3] = As[(base + 8) * GS_STR + kk + qq + 4];
            }
#pragma unroll
            for (int nf = 0; nf < 4; nf++) {
                const int col = warp_n * 32 + nf * 8 + qd;
                uint32_t bfr[2];
                bfr[0] = Ws[col * GS_STR + kk + qq];
                bfr[1] = Ws[col * GS_STR + kk + qq + 4];
#pragma unroll
                for (int mf = 0; mf < 4; mf++)
                    mma_tf32(acc[mf][nf], a[mf], bfr);
            }
        }
    }

#pragma unroll
    for (int mf = 0; mf < 4; mf++) {
        const int row0 = m0 + warp_m * 64 + mf * 16 + qd;
        const int row1 = row0 + 8;
#pragma unroll
        for (int nf = 0; nf < 4; nf++) {
            const int col = n0 + warp_n * 32 + nf * 8 + 2 * qq;
            float2 o0, o1;
            o0.x = acc[mf][nf][0]; o0.y = acc[mf][nf][1];
            o1.x = acc[mf][nf][2]; o1.y = acc[mf][nf][3];
            if (BIAS) {
                const float2 bv = *(const float2*)&bias[col];
                o0.x += bv.x; o0.y += bv.y;
                o1.x += bv.x; o1.y += bv.y;
            }
            if (OUT_TF32) {
                o0.x = __uint_as_float(f2tf(o0.x)); o0.y = __uint_as_float(f2tf(o0.y));
                o1.x = __uint_as_float(f2tf(o1.x)); o1.y = __uint_as_float(f2tf(o1.y));
            }
            *(float2*)&C[(size_t)row0 * NC + col] = o0;
            *(float2*)&C[(size_t)row1 * NC + col] = o1;
        }
    }
}

// ---------------------------------------------------------------------------
// Kernel A: global logits. For (b, kh): gl[i,j] = q_kh[i] . k_kh[j], K=64.
// ---------------------------------------------------------------------------
__global__ void __launch_bounds__(256, 2) gl_gemm(const float* __restrict__ QK,
                                                  float* __restrict__ GL)
{
    __shared__ uint32_t As[128 * GS_STR];
    __shared__ uint32_t Ws[128 * GS_STR];

    const int b  = blockIdx.z >> 2;
    const int kh = blockIdx.z & 3;
    const int m0 = blockIdx.y * 128;
    const int n0 = blockIdx.x * 128;
    const int tid = threadIdx.x;
    const int lane = tid & 31;
    const int warp = tid >> 5;
    const int warp_m = warp >> 2;
    const int warp_n = warp & 3;
    const int qd = lane >> 2;
    const int qq = lane & 3;

    const int lr = tid >> 1;
    const int lc = (tid & 1) * 16;

    const uint32_t* Ap = (const uint32_t*)QK + (size_t)(b * SEQ + m0 + lr) * 512 + kh * HD + lc;
    const uint32_t* Wp = (const uint32_t*)QK + (size_t)(b * SEQ + n0 + lr) * 512 + 256 + kh * HD + lc;
    uint32_t* Asd = &As[lr * GS_STR + lc];
    uint32_t* Wsd = &Ws[lr * GS_STR + lc];

    float acc[4][4][4];
#pragma unroll
    for (int mf = 0; mf < 4; mf++)
#pragma unroll
        for (int nf = 0; nf < 4; nf++)
#pragma unroll
            for (int c = 0; c < 4; c++) acc[mf][nf][c] = 0.f;

    uint4 av[4], wv[4];
#pragma unroll
    for (int i = 0; i < 4; i++) {
        av[i] = *(const uint4*)(Ap + i * 4);
        wv[i] = *(const uint4*)(Wp + i * 4);
    }

#pragma unroll
    for (int k0 = 0; k0 < HD; k0 += 32) {
        __syncthreads();
#pragma unroll
        for (int i = 0; i < 4; i++) {
            *(uint4*)(Asd + i * 4) = av[i];
            *(uint4*)(Wsd + i * 4) = wv[i];
        }
        __syncthreads();

        if (k0 + 32 < HD) {
#pragma unroll
            for (int i = 0; i < 4; i++) {
                av[i] = *(const uint4*)(Ap + k0 + 32 + i * 4);
                wv[i] = *(const uint4*)(Wp + k0 + 32 + i * 4);
            }
        }

#pragma unroll
        for (int kk = 0; kk < 32; kk += 8) {
            uint32_t a[4][4];
#pragma unroll
            for (int mf = 0; mf < 4; mf++) {
                const int base = warp_m * 64 + mf * 16 + qd;
                a[mf][0] = As[base * GS_STR + kk + qq];
                a[mf][1] = As[(base + 8) * GS_STR + kk + qq];
                a[mf][2] = As[base * GS_STR + kk + qq + 4];
                a[mf][3] = As[(base + 8) * GS_STR + kk + qq + 4];
            }
#pragma unroll
            for (int nf = 0; nf < 4; nf++) {
                const int col = warp_n * 32 + nf * 8 + qd;
                uint32_t bfr[2];
                bfr[0] = Ws[col * GS_STR + kk + qq];
                bfr[1] = Ws[col * GS_STR + kk + qq + 4];
#pragma unroll
                for (int mf = 0; mf < 4; mf++)
                    mma_tf32(acc[mf][nf], a[mf], bfr);
            }
        }
    }

    float* Cp = GL + (size_t)blockIdx.z * SEQ * SEQ;
#pragma unroll
    for (int mf = 0; mf < 4; mf++) {
        const int row0 = m0 + warp_m * 64 + mf * 16 + qd;
        const int row1 = row0 + 8;
#pragma unroll
        for (int nf = 0; nf < 4; nf++) {
            const int col = n0 + warp_n * 32 + nf * 8 + 2 * qq;
            float2 o0, o1;
            o0.x = acc[mf][nf][0]; o0.y = acc[mf][nf][1];
            o1.x = acc[mf][nf][2]; o1.y = acc[mf][nf][3];
            *(float2*)&Cp[(size_t)row0 * SEQ + col] = o0;
            *(float2*)&Cp[(size_t)row1 * SEQ + col] = o1;
        }
    }
}

// ---------------------------------------------------------------------------
// Kernel B: mix + softmax + AV. 4 heads per CTA (512 threads), Sg staged in
// smem (coalesced cp.async, shared by all heads). One warp owns 16 full S
// rows -> softmax is warp-local (no stats smem / barriers). V pipelined at
// half-tile granularity with wait_group accounting + per-head named bars.
// ---------------------------------------------------------------------------
#define HPC    4
#define SG_STR 68
#define SG_K   (64 * SG_STR)
#define VS_STR 68
#define PS_STR 68

__global__ void __launch_bounds__(512) fish_mix_attn(const float* __restrict__ mixl,
                                                     const float* __restrict__ GL,
                                                     float* __restrict__ ctx)
{
    extern __shared__ float sm[];
    float* Sg    = sm;                          // [4k][64][SG_STR], shared by heads
    float* VsAll = Sg + 4 * SG_K;               // [4 heads][64][VS_STR]
    float* PsAll = VsAll + HPC * 64 * VS_STR;   // [4 heads][64][PS_STR]

    const int i0   = blockIdx.x * 64;
    const int b    = blockIdx.z;
    const int tid  = threadIdx.x;
    const int hh   = tid >> 7;                  // 0..3 head slot
    const int t    = tid & 127;
    const int h    = blockIdx.y * HPC + hh;
    const int lane = tid & 31;
    const int w4   = t >> 5;                    // warp within head: 0..3
    const int qd   = lane >> 2;
    const int qq   = lane & 3;
    const int bar_id = hh + 1;

    const int row0 = 16 * w4 + qd;              // absolute S row (c0/c1)
    const int row1 = row0 + 8;                  // (c2/c3)

    float* Vs = VsAll + hh * 64 * VS_STR;
    float* Ps = PsAll + hh * 64 * PS_STR;

    // Sg copy slots (512 threads, 16B chunks): 256 logical rows (4k x 64)
    const int gc = (tid & 15) * 4;
    const int gr = tid >> 4;                    // 0..31
    // V copy slots (128 threads/head): 8 rows/pass
    const int vc = (t & 15) * 4;
    const int vr = t >> 4;                      // 0..7
    const uint32_t SgA = (uint32_t)__cvta_generic_to_shared(Sg);
    const uint32_t VsA = (uint32_t)__cvta_generic_to_shared(Vs);

    // Prologue: group1 = Sg(0) + Vlow(0); group2 = Vhigh(0)
#pragma unroll
    for (int i = 0; i < 8; i++) {
        const int r = gr + 32 * i;
        const int k = r >> 6, rr = r & 63;
        cp16(SgA + (uint32_t)((k * 64 + rr) * SG_STR + gc) * 4,
             &GL[((size_t)(b * KG + k) * SEQ + i0 + rr) * SEQ + 0 + gc]);
    }
#pragma unroll
    for (int i = 0; i < 4; i++) {
        const int r = vr + 8 * i;
        cp16(VsA + (uint32_t)(r * VS_STR + vc) * 4,
             &g_v[((size_t)(b * SEQ + 0 + r)) * DIM + h * HD + vc]);
    }
    cp_commit();
#pragma unroll
    for (int i = 0; i < 4; i++) {
        const int r = 32 + vr + 8 * i;
        cp16(VsA + (uint32_t)(r * VS_STR + vc) * 4,
             &g_v[((size_t)(b * SEQ + 0 + r)) * DIM + h * HD + vc]);
    }
    cp_commit();

    // mixw = softmax(mix_logits[h,:]) * HEAD_DIM^-0.5
    float ml0 = mixl[h * KG + 0], ml1 = mixl[h * KG + 1];
    float ml2 = mixl[h * KG + 2], ml3 = mixl[h * KG + 3];
    float mm = fmaxf(fmaxf(ml0, ml1), fmaxf(ml2, ml3));
    float e0 = expf(ml0 - mm), e1 = expf(ml1 - mm);
    float e2 = expf(ml2 - mm), e3 = expf(ml3 - mm);
    float inv_es = 0.125f / (e0 + e1 + e2 + e3);
    const float mw0 = e0 * inv_es, mw1 = e1 * inv_es;
    const float mw2 = e2 * inv_es, mw3 = e3 * inv_es;

    float O[8][4];
#pragma unroll
    for (int nt = 0; nt < 8; nt++)
#pragma unroll
        for (int c = 0; c < 4; c++) O[nt][c] = 0.f;
    float m_0 = -INFINITY, m_1 = -INFINITY, l_0 = 0.f, l_1 = 0.f;

    const uint32_t* Psu = (const uint32_t*)Ps;
    const uint32_t* Vsu = (const uint32_t*)Vs;
    const uint32_t* pa0 = Psu + row0 * PS_STR + qq;
    const uint32_t* pa1 = Psu + row1 * PS_STR + qq;
    const float* mixbase = Sg + row0 * SG_STR + 2 * qq;

    for (int j0 = 0; j0 < SEQ; j0 += 64) {
        const bool more = (j0 + 64 < SEQ);

        cp_wait1();          // Sg(j) + Vlow(j) landed; Vhigh(j) may be in flight
        __syncthreads();     // visibility; all prior Sg reads long done

        // ---- mix: S = sum_k mixw[k] * Sg_k (warp-local fragment positions) ----
        float S[8][4];
#pragma unroll
        for (int nt = 0; nt < 8; nt++) {
            const float* p = mixbase + nt * 8;
            float2 a0 = *(const float2*)(p);
            float2 a1 = *(const float2*)(p + 8 * SG_STR);
            float2 b0 = *(const float2*)(p + SG_K);
            float2 b1 = *(const float2*)(p + SG_K + 8 * SG_STR);
            float2 c0 = *(const float2*)(p + 2 * SG_K);
            float2 c1 = *(const float2*)(p + 2 * SG_K + 8 * SG_STR);
            float2 d0 = *(const float2*)(p + 3 * SG_K);
            float2 d1 = *(const float2*)(p + 3 * SG_K + 8 * SG_STR);
            S[nt][0] = mw0 * a0.x + mw1 * b0.x + mw2 * c0.x + mw3 * d0.x;
            S[nt][1] = mw0 * a0.y + mw1 * b0.y + mw2 * c0.y + mw3 * d0.y;
            S[nt][2] = mw0 * a1.x + mw1 * b1.x + mw2 * c1.x + mw3 * d1.x;
            S[nt][3] = mw0 * a1.y + mw1 * b1.y + mw2 * c1.y + mw3 * d1.y;
        }
        __syncthreads();     // all Sg(j) reads done -> safe to refill

        if (more) {          // Sg(j+1) prefetch overlaps softmax + AV
#pragma unroll
            for (int i = 0; i < 8; i++) {
                const int r = gr + 32 * i;
                const int k = r >> 6, rr = r & 63;
                cp16(SgA + (uint32_t)((k * 64 + rr) * SG_STR + gc) * 4,
                     &GL[((size_t)(b * KG + k) * SEQ + i0 + rr) * SEQ + j0 + 64 + gc]);
            }
            cp_commit();     // group A'
        }

        // ---- warp-local online softmax (full row within quad) ----
        float mx0 = fmaxf(S[0][0], S[0][1]), mx1 = fmaxf(S[0][2], S[0][3]);
#pragma unroll
        for (int nt = 1; nt < 8; nt++) {
            mx0 = fmaxf(mx0, fmaxf(S[nt][0], S[nt][1]));
            mx1 = fmaxf(mx1, fmaxf(S[nt][2], S[nt][3]));
        }
        mx0 = fmaxf(mx0, __shfl_xor_sync(0xffffffffu, mx0, 1));
        mx0 = fmaxf(mx0, __shfl_xor_sync(0xffffffffu, mx0, 2));
        mx1 = fmaxf(mx1, __shfl_xor_sync(0xffffffffu, mx1, 1));
        mx1 = fmaxf(mx1, __shfl_xor_sync(0xffffffffu, mx1, 2));
        const float mn0 = fmaxf(m_0, mx0), mn1 = fmaxf(m_1, mx1);
        const float corr0 = __expf(m_0 - mn0), corr1 = __expf(m_1 - mn1);
        m_0 = mn0; m_1 = mn1;

        float rs0 = 0.f, rs1 = 0.f;
#pragma unroll
        for (int nt = 0; nt < 8; nt++) {
            const float p0 = __expf(S[nt][0] - mn0);
            const float p1 = __expf(S[nt][1] - mn0);
            const float p2 = __expf(S[nt][2] - mn1);
            const float p3 = __expf(S[nt][3] - mn1);
            rs0 += p0 + p1; rs1 += p2 + p3;
            const int col = nt * 8 + 2 * qq;
            uint2 w0, w1;
            w0.x = f2tf(p0); w0.y = f2tf(p1);
            w1.x = f2tf(p2); w1.y = f2tf(p3);
            *(uint2*)&Ps[row0 * PS_STR + col] = w0;
            *(uint2*)&Ps[row1 * PS_STR + col] = w1;
            O[nt][0] *= corr0; O[nt][1] *= corr0;
            O[nt][2] *= corr1; O[nt][3] *= corr1;
        }
        rs0 += __shfl_xor_sync(0xffffffffu, rs0, 1);
        rs0 += __shfl_xor_sync(0xffffffffu, rs0, 2);
        rs1 += __shfl_xor_sync(0xffffffffu, rs1, 1);
        rs1 += __shfl_xor_sync(0xffffffffu, rs1, 2);
        l_0 = l_0 * corr0 + rs0;
        l_1 = l_1 * corr1 + rs1;
        __syncwarp();        // Ps rows of this warp complete (same-warp consumer)

        // ---- O += P V, low half (k0 = 0..24) ----
#pragma unroll
        for (int k0 = 0; k0 < 32; k0 += 8) {
            uint32_t a[4];
            a[0] = pa0[k0]; a[1] = pa1[k0];
            a[2] = pa0[k0 + 4]; a[3] = pa1[k0 + 4];
#pragma unroll
            for (int nt = 0; nt < 8; nt++) {
                const int d = nt * 8 + qd;
                uint32_t bf[2];
                bf[0] = Vsu[(k0 + qq) * VS_STR + d];
                bf[1] = Vsu[(k0 + qq + 4) * VS_STR + d];
                mma_tf32(O[nt], a, bf);
            }
        }

        // Vhigh(j) must be visible; Vlow(j) reads done -> refill low with j+1
        if (more) cp_wait1(); else cp_wait_all();
        bar_named(bar_id, 128);
        if (more) {
#pragma unroll
            for (int i = 0; i < 4; i++) {
                const int r = vr + 8 * i;
                cp16(VsA + (uint32_t)(r * VS_STR + vc) * 4,
                     &g_v[((size_t)(b * SEQ + j0 + 64 + r)) * DIM + h * HD + vc]);
            }
            cp_commit();     // group B'
        }

        // ---- O += P V, high half (k0 = 32..56) ----
#pragma unroll
        for (int k0 = 32; k0 < 64; k0 += 8) {
            uint32_t a[4];
            a[0] = pa0[k0]; a[1] = pa1[k0];
            a[2] = pa0[k0 + 4]; a[3] = pa1[k0 + 4];
#pragma unroll
            for (int nt = 0; nt < 8; nt++) {
                const int d = nt * 8 + qd;
                uint32_t bf[2];
                bf[0] = Vsu[(k0 + qq) * VS_STR + d];
                bf[1] = Vsu[(k0 + qq + 4) * VS_STR + d];
                mma_tf32(O[nt], a, bf);
            }
        }

        bar_named(bar_id, 128);   // high reads done -> safe to refill high
        if (more) {
#pragma unroll
            for (int i = 0; i < 4; i++) {
                const int r = 32 + vr + 8 * i;
                cp16(VsA + (uint32_t)(r * VS_STR + vc) * 4,
                     &g_v[((size_t)(b * SEQ + j0 + 64 + r)) * DIM + h * HD + vc]);
            }
            cp_commit();     // group C'
        }
    }

    // Epilogue: normalize, write ctx (B,N,768) fp32
    const float inv0 = 1.f / l_0, inv1 = 1.f / l_1;
    const size_t r0off = ((size_t)(b * SEQ + i0 + row0)) * DIM + h * HD;
    const size_t r1off = ((size_t)(b * SEQ + i0 + row1)) * DIM + h * HD;
#pragma unroll
    for (int nt = 0; nt < 8; nt++) {
        const int col = nt * 8 + 2 * qq;
        float2 o0; o0.x = O[nt][0] * inv0; o0.y = O[nt][1] * inv0;
        float2 o1; o1.x = O[nt][2] * inv1; o1.y = O[nt][3] * inv1;
        *(float2*)&ctx[r0off + col] = o0;
        *(float2*)&ctx[r1off + col] = o1;
    }
}

// ---------------------------------------------------------------------------
// Launch
// ---------------------------------------------------------------------------
extern "C" void kernel_launch(void* const* d_in, const int* in_sizes, int n_in,
                              void* d_out, int out_size)
{
    const float* x      = (const float*)d_in[0];
    const float* w_qkv  = (const float*)d_in[1];
    const float* mixl   = (const float*)d_in[2];
    const float* w_v    = (const float*)d_in[3];
    const float* w_proj = (const float*)d_in[4];
    const float* b_proj = (const float*)d_in[5];
    float* out = (float*)d_out;

    float *qk, *v, *ctx, *gl;
    cudaGetSymbolAddress((void**)&qk,  g_qk);
    cudaGetSymbolAddress((void**)&v,   g_v);
    cudaGetSymbolAddress((void**)&ctx, g_ctx);
    cudaGetSymbolAddress((void**)&gl,  g_gl);

    const int attn_smem = (4 * SG_K + HPC * 64 * VS_STR + HPC * 64 * PS_STR)
                          * (int)sizeof(float);
    cudaFuncSetAttribute(fish_mix_attn, cudaFuncAttributeMaxDynamicSharedMemorySize, attn_smem);

    // 1) qk = x @ w_qkv[0:512]^T  -> tf32 bits
    tf32_gemm_nt<512, true, false><<<dim3(4, 64), 256>>>(x, w_qkv, nullptr, qk);
    // 2) v = x @ w_v^T            -> tf32 bits
    tf32_gemm_nt<768, true, false><<<dim3(6, 64), 256>>>(x, w_v, nullptr, v);
    // A) global logits per (b, k-head): gl = q_k . k_k^T  (fp32 raw)
    gl_gemm<<<dim3(8, 8, BB * KG), 256>>>(qk, gl);
    // B) mix + softmax + AV, 4 heads/CTA, warp-local softmax
    fish_mix_attn<<<dim3(SEQ / 64, NH / HPC, BB), 512, attn_smem>>>(mixl, gl, ctx);
    // 4) out = ctx @ w_proj^T + b_proj (fp32 out)
    tf32_gemm_nt<768, false, true><<<dim3(6, 64), 256>>>(ctx, w_proj, b_proj, out);
}

// round 10
// speedup vs baseline: 1.3940x; 1.2410x over previous
#include <cuda_runtime.h>
#include <math.h>
#include <stdint.h>

// Problem constants
#define BB   8
#define SEQ  1024
#define DIM  768
#define NH   12
#define KG   4
#define HD   64
#define MTOT (BB*SEQ)     // 8192

// Scratch (static device globals — no runtime allocation allowed)
// g_qk / g_v hold TF32 bit patterns (converted in GEMM epilogue).
__device__ float g_qk[(size_t)MTOT * 512];   // per row: [0,256)=q heads, [256,512)=k heads
__device__ float g_v [(size_t)MTOT * DIM];
__device__ float g_ctx[(size_t)MTOT * DIM];
__device__ float g_gl[(size_t)BB * KG * SEQ * SEQ];   // raw global logits q_k . k_k^T

// ---------------------------------------------------------------------------
// TF32 / cp.async helpers
// ---------------------------------------------------------------------------
__device__ __forceinline__ uint32_t f2tf(float x) {
    uint32_t r;
    asm("cvt.rna.tf32.f32 %0, %1;" : "=r"(r) : "f"(x));
    return r;
}

__device__ __forceinline__ void mma_tf32(float* d, const uint32_t* a, const uint32_t* b) {
    asm volatile(
        "mma.sync.aligned.m16n8k8.row.col.f32.tf32.tf32.f32 "
        "{%0,%1,%2,%3}, {%4,%5,%6,%7}, {%8,%9}, {%0,%1,%2,%3};"
        : "+f"(d[0]), "+f"(d[1]), "+f"(d[2]), "+f"(d[3])
        : "r"(a[0]), "r"(a[1]), "r"(a[2]), "r"(a[3]), "r"(b[0]), "r"(b[1]));
}

__device__ __forceinline__ void cp16(uint32_t smem_dst, const void* gsrc) {
    asm volatile("cp.async.cg.shared.global [%0], [%1], 16;"
                 :: "r"(smem_dst), "l"(gsrc));
}
__device__ __forceinline__ void cp_commit() {
    asm volatile("cp.async.commit_group;");
}
__device__ __forceinline__ void cp_wait_all() {
    asm volatile("cp.async.wait_group 0;");
}
__device__ __forceinline__ void cp_wait1() {
    asm volatile("cp.async.wait_group 1;");
}
__device__ __forceinline__ void bar_named(int id, int nthreads) {
    asm volatile("bar.sync %0, %1;" :: "r"(id), "r"(nthreads) : "memory");
}

// ---------------------------------------------------------------------------
// TF32 tensor-core GEMM: C[M, NC] = A[M, 768] @ W[NC, 768]^T (+ bias).
// ---------------------------------------------------------------------------
#define GS_STR 36

template<int NC, bool OUT_TF32, bool BIAS>
__global__ void __launch_bounds__(256, 2) tf32_gemm_nt(const float* __restrict__ A,
                                                       const float* __restrict__ W,
                                                       const float* __restrict__ bias,
                                                       float* __restrict__ C)
{
    __shared__ uint32_t As[128 * GS_STR];
    __shared__ uint32_t Ws[128 * GS_STR];

    const int m0  = blockIdx.y * 128;
    const int n0  = blockIdx.x * 128;
    const int tid = threadIdx.x;
    const int lane = tid & 31;
    const int warp = tid >> 5;
    const int warp_m = warp >> 2;
    const int warp_n = warp & 3;
    const int qd = lane >> 2;
    const int qq = lane & 3;

    const int lr = tid >> 1;
    const int lc = (tid & 1) * 16;

    const float* Ap = A + (size_t)(m0 + lr) * DIM + lc;
    const float* Wp = W + (size_t)(n0 + lr) * DIM + lc;
    uint32_t* Asd = &As[lr * GS_STR + lc];
    uint32_t* Wsd = &Ws[lr * GS_STR + lc];

    float acc[4][4][4];
#pragma unroll
    for (int mf = 0; mf < 4; mf++)
#pragma unroll
        for (int nf = 0; nf < 4; nf++)
#pragma unroll
            for (int c = 0; c < 4; c++) acc[mf][nf][c] = 0.f;

    float4 av[4], wv[4];
#pragma unroll
    for (int i = 0; i < 4; i++) {
        av[i] = *(const float4*)(Ap + i * 4);
        wv[i] = *(const float4*)(Wp + i * 4);
    }

    for (int k0 = 0; k0 < DIM; k0 += 32) {
        __syncthreads();
#pragma unroll
        for (int i = 0; i < 4; i++) {
            uint4 at, wt;
            at.x = f2tf(av[i].x); at.y = f2tf(av[i].y);
            at.z = f2tf(av[i].z); at.w = f2tf(av[i].w);
            wt.x = f2tf(wv[i].x); wt.y = f2tf(wv[i].y);
            wt.z = f2tf(wv[i].z); wt.w = f2tf(wv[i].w);
            *(uint4*)(Asd + i * 4) = at;
            *(uint4*)(Wsd + i * 4) = wt;
        }
        __syncthreads();

        if (k0 + 32 < DIM) {
#pragma unroll
            for (int i = 0; i < 4; i++) {
                av[i] = *(const float4*)(Ap + k0 + 32 + i * 4);
                wv[i] = *(const float4*)(Wp + k0 + 32 + i * 4);
            }
        }

#pragma unroll
        for (int kk = 0; kk < 32; kk += 8) {
            uint32_t a[4][4];
#pragma unroll
            for (int mf = 0; mf < 4; mf++) {
                const int base = warp_m * 64 + mf * 16 + qd;
                a[mf][0] = As[base * GS_STR + kk + qq];
                a[mf][1] = As[(base + 8) * GS_STR + kk + qq];
                a[mf][2] = As[base * GS_STR + kk + qq + 4];
                a[mf][3] = As[(base + 8) * GS_STR + kk + qq + 4];
            }
#pragma unroll
            for (int nf = 0; nf < 4; nf++) {
                const int col = warp_n * 32 + nf * 8 + qd;
                uint32_t bfr[2];
                bfr[0] = Ws[col * GS_STR + kk + qq];
                bfr[1] = Ws[col * GS_STR + kk + qq + 4];
#pragma unroll
                for (int mf = 0; mf < 4; mf++)
                    mma_tf32(acc[mf][nf], a[mf], bfr);
            }
        }
    }

#pragma unroll
    for (int mf = 0; mf < 4; mf++) {
        const int row0 = m0 + warp_m * 64 + mf * 16 + qd;
        const int row1 = row0 + 8;
#pragma unroll
        for (int nf = 0; nf < 4; nf++) {
            const int col = n0 + warp_n * 32 + nf * 8 + 2 * qq;
            float2 o0, o1;
            o0.x = acc[mf][nf][0]; o0.y = acc[mf][nf][1];
            o1.x = acc[mf][nf][2]; o1.y = acc[mf][nf][3];
            if (BIAS) {
                const float2 bv = *(const float2*)&bias[col];
                o0.x += bv.x; o0.y += bv.y;
                o1.x += bv.x; o1.y += bv.y;
            }
            if (OUT_TF32) {
                o0.x = __uint_as_float(f2tf(o0.x)); o0.y = __uint_as_float(f2tf(o0.y));
                o1.x = __uint_as_float(f2tf(o1.x)); o1.y = __uint_as_float(f2tf(o1.y));
            }
            *(float2*)&C[(size_t)row0 * NC + col] = o0;
            *(float2*)&C[(size_t)row1 * NC + col] = o1;
        }
    }
}

// ---------------------------------------------------------------------------
// Kernel A: global logits. For (b, kh): gl[i,j] = q_kh[i] . k_kh[j], K=64.
// ---------------------------------------------------------------------------
__global__ void __launch_bounds__(256, 2) gl_gemm(const float* __restrict__ QK,
                                                  float* __restrict__ GL)
{
    __shared__ uint32_t As[128 * GS_STR];
    __shared__ uint32_t Ws[128 * GS_STR];

    const int b  = blockIdx.z >> 2;
    const int kh = blockIdx.z & 3;
    const int m0 = blockIdx.y * 128;
    const int n0 = blockIdx.x * 128;
    const int tid = threadIdx.x;
    const int lane = tid & 31;
    const int warp = tid >> 5;
    const int warp_m = warp >> 2;
    const int warp_n = warp & 3;
    const int qd = lane >> 2;
    const int qq = lane & 3;

    const int lr = tid >> 1;
    const int lc = (tid & 1) * 16;

    const uint32_t* Ap = (const uint32_t*)QK + (size_t)(b * SEQ + m0 + lr) * 512 + kh * HD + lc;
    const uint32_t* Wp = (const uint32_t*)QK + (size_t)(b * SEQ + n0 + lr) * 512 + 256 + kh * HD + lc;
    uint32_t* Asd = &As[lr * GS_STR + lc];
    uint32_t* Wsd = &Ws[lr * GS_STR + lc];

    float acc[4][4][4];
#pragma unroll
    for (int mf = 0; mf < 4; mf++)
#pragma unroll
        for (int nf = 0; nf < 4; nf++)
#pragma unroll
            for (int c = 0; c < 4; c++) acc[mf][nf][c] = 0.f;

    uint4 av[4], wv[4];
#pragma unroll
    for (int i = 0; i < 4; i++) {
        av[i] = *(const uint4*)(Ap + i * 4);
        wv[i] = *(const uint4*)(Wp + i * 4);
    }

#pragma unroll
    for (int k0 = 0; k0 < HD; k0 += 32) {
        __syncthreads();
#pragma unroll
        for (int i = 0; i < 4; i++) {
            *(uint4*)(Asd + i * 4) = av[i];
            *(uint4*)(Wsd + i * 4) = wv[i];
        }
        __syncthreads();

        if (k0 + 32 < HD) {
#pragma unroll
            for (int i = 0; i < 4; i++) {
                av[i] = *(const uint4*)(Ap + k0 + 32 + i * 4);
                wv[i] = *(const uint4*)(Wp + k0 + 32 + i * 4);
            }
        }

#pragma unroll
        for (int kk = 0; kk < 32; kk += 8) {
            uint32_t a[4][4];
#pragma unroll
            for (int mf = 0; mf < 4; mf++) {
                const int base = warp_m * 64 + mf * 16 + qd;
                a[mf][0] = As[base * GS_STR + kk + qq];
                a[mf][1] = As[(base + 8) * GS_STR + kk + qq];
                a[mf][2] = As[base * GS_STR + kk + qq + 4];
                a[mf][3] = As[(base + 8) * GS_STR + kk + qq + 4];
            }
#pragma unroll
            for (int nf = 0; nf < 4; nf++) {
                const int col = warp_n * 32 + nf * 8 + qd;
                uint32_t bfr[2];
                bfr[0] = Ws[col * GS_STR + kk + qq];
                bfr[1] = Ws[col * GS_STR + kk + qq + 4];
#pragma unroll
                for (int mf = 0; mf < 4; mf++)
                    mma_tf32(acc[mf][nf], a[mf], bfr);
            }
        }
    }

    float* Cp = GL + (size_t)blockIdx.z * SEQ * SEQ;
#pragma unroll
    for (int mf = 0; mf < 4; mf++) {
        const int row0 = m0 + warp_m * 64 + mf * 16 + qd;
        const int row1 = row0 + 8;
#pragma unroll
        for (int nf = 0; nf < 4; nf++) {
            const int col = n0 + warp_n * 32 + nf * 8 + 2 * qq;
            float2 o0, o1;
            o0.x = acc[mf][nf][0]; o0.y = acc[mf][nf][1];
            o1.x = acc[mf][nf][2]; o1.y = acc[mf][nf][3];
            *(float2*)&Cp[(size_t)row0 * SEQ + col] = o0;
            *(float2*)&Cp[(size_t)row1 * SEQ + col] = o1;
        }
    }
}

// ---------------------------------------------------------------------------
// Kernel B: mix + softmax + AV. 2 heads per CTA (256 threads, 2 CTAs/SM).
// P stays in REGISTERS: the mix output at cols (2qq, 2qq+1) is fed directly
// as the AV MMA A-fragment, with V's B-fragment rows permuted to match
// (k-lane permutation is valid when applied to both operands). No Ps smem.
// ---------------------------------------------------------------------------
#define HPC    2
#define SG_STR 72
#define SG_K   (64 * SG_STR)
#define VS_STR 68

__global__ void __launch_bounds__(256, 2) fish_mix_attn(const float* __restrict__ mixl,
                                                        const float* __restrict__ GL,
                                                        float* __restrict__ ctx)
{
    extern __shared__ float sm[];
    float* Sg    = sm;                          // [4k][64][SG_STR], shared by heads
    float* VsAll = Sg + 4 * SG_K;               // [2 heads][64][VS_STR]

    const int i0   = blockIdx.x * 64;
    const int b    = blockIdx.z;
    const int tid  = threadIdx.x;
    const int hh   = tid >> 7;                  // 0..1 head slot
    const int t    = tid & 127;
    const int h    = blockIdx.y * HPC + hh;
    const int lane = tid & 31;
    const int w4   = t >> 5;                    // warp within head: 0..3
    const int qd   = lane >> 2;
    const int qq   = lane & 3;
    const int bar_id = hh + 1;

    const int row0 = 16 * w4 + qd;
    const int row1 = row0 + 8;

    float* Vs = VsAll + hh * 64 * VS_STR;

    // Sg copy slots (256 threads, 16B chunks): 256 logical rows (4k x 64)
    const int gc = (tid & 15) * 4;
    const int gr = tid >> 4;                    // 0..15
    // V copy slots (128 threads/head): 8 rows/pass
    const int vc = (t & 15) * 4;
    const int vr = t >> 4;                      // 0..7
    const uint32_t SgA = (uint32_t)__cvta_generic_to_shared(Sg);
    const uint32_t VsA = (uint32_t)__cvta_generic_to_shared(Vs);

    // Prologue: group1 = Sg(0) + Vlow(0); group2 = Vhigh(0)
#pragma unroll
    for (int i = 0; i < 16; i++) {
        const int r = gr + 16 * i;
        const int k = r >> 6, rr = r & 63;
        cp16(SgA + (uint32_t)((k * 64 + rr) * SG_STR + gc) * 4,
             &GL[((size_t)(b * KG + k) * SEQ + i0 + rr) * SEQ + 0 + gc]);
    }
#pragma unroll
    for (int i = 0; i < 4; i++) {
        const int r = vr + 8 * i;
        cp16(VsA + (uint32_t)(r * VS_STR + vc) * 4,
             &g_v[((size_t)(b * SEQ + 0 + r)) * DIM + h * HD + vc]);
    }
    cp_commit();
#pragma unroll
    for (int i = 0; i < 4; i++) {
        const int r = 32 + vr + 8 * i;
        cp16(VsA + (uint32_t)(r * VS_STR + vc) * 4,
             &g_v[((size_t)(b * SEQ + 0 + r)) * DIM + h * HD + vc]);
    }
    cp_commit();

    // mixw = softmax(mix_logits[h,:]) * HEAD_DIM^-0.5
    float ml0 = mixl[h * KG + 0], ml1 = mixl[h * KG + 1];
    float ml2 = mixl[h * KG + 2], ml3 = mixl[h * KG + 3];
    float mm = fmaxf(fmaxf(ml0, ml1), fmaxf(ml2, ml3));
    float e0 = expf(ml0 - mm), e1 = expf(ml1 - mm);
    float e2 = expf(ml2 - mm), e3 = expf(ml3 - mm);
    float inv_es = 0.125f / (e0 + e1 + e2 + e3);
    const float mw0 = e0 * inv_es, mw1 = e1 * inv_es;
    const float mw2 = e2 * inv_es, mw3 = e3 * inv_es;

    float O[8][4];
#pragma unroll
    for (int nt = 0; nt < 8; nt++)
#pragma unroll
        for (int c = 0; c < 4; c++) O[nt][c] = 0.f;
    float m_0 = -INFINITY, m_1 = -INFINITY, l_0 = 0.f, l_1 = 0.f;

    const uint32_t* Vsu = (const uint32_t*)Vs;
    const float* mixbase = Sg + row0 * SG_STR + 2 * qq;

    for (int j0 = 0; j0 < SEQ; j0 += 64) {
        const bool more = (j0 + 64 < SEQ);

        cp_wait1();          // Sg(j) + Vlow(j) landed; Vhigh(j) may be in flight
        __syncthreads();     // visibility; all prior Sg reads long done

        // ---- mix: S = sum_k mixw[k] * Sg_k ----
        float S[8][4];
#pragma unroll
        for (int nt = 0; nt < 8; nt++) {
            const float* p = mixbase + nt * 8;
            float2 a0 = *(const float2*)(p);
            float2 a1 = *(const float2*)(p + 8 * SG_STR);
            float2 b0 = *(const float2*)(p + SG_K);
            float2 b1 = *(const float2*)(p + SG_K + 8 * SG_STR);
            float2 c0 = *(const float2*)(p + 2 * SG_K);
            float2 c1 = *(const float2*)(p + 2 * SG_K + 8 * SG_STR);
            float2 d0 = *(const float2*)(p + 3 * SG_K);
            float2 d1 = *(const float2*)(p + 3 * SG_K + 8 * SG_STR);
            S[nt][0] = mw0 * a0.x + mw1 * b0.x + mw2 * c0.x + mw3 * d0.x;  // r0,c0
            S[nt][1] = mw0 * a0.y + mw1 * b0.y + mw2 * c0.y + mw3 * d0.y;  // r0,c1
            S[nt][2] = mw0 * a1.x + mw1 * b1.x + mw2 * c1.x + mw3 * d1.x;  // r1,c0
            S[nt][3] = mw0 * a1.y + mw1 * b1.y + mw2 * c1.y + mw3 * d1.y;  // r1,c1
        }
        __syncthreads();     // all Sg(j) reads done -> safe to refill

        if (more) {          // Sg(j+1) prefetch overlaps softmax + AV
#pragma unroll
            for (int i = 0; i < 16; i++) {
                const int r = gr + 16 * i;
                const int k = r >> 6, rr = r & 63;
                cp16(SgA + (uint32_t)((k * 64 + rr) * SG_STR + gc) * 4,
                     &GL[((size_t)(b * KG + k) * SEQ + i0 + rr) * SEQ + j0 + 64 + gc]);
            }
            cp_commit();     // group A'
        }

        // ---- warp-local online softmax ----
        float mx0 = fmaxf(S[0][0], S[0][1]), mx1 = fmaxf(S[0][2], S[0][3]);
#pragma unroll
        for (int nt = 1; nt < 8; nt++) {
            mx0 = fmaxf(mx0, fmaxf(S[nt][0], S[nt][1]));
            mx1 = fmaxf(mx1, fmaxf(S[nt][2], S[nt][3]));
        }
        mx0 = fmaxf(mx0, __shfl_xor_sync(0xffffffffu, mx0, 1));
        mx0 = fmaxf(mx0, __shfl_xor_sync(0xffffffffu, mx0, 2));
        mx1 = fmaxf(mx1, __shfl_xor_sync(0xffffffffu, mx1, 1));
        mx1 = fmaxf(mx1, __shfl_xor_sync(0xffffffffu, mx1, 2));
        const float mn0 = fmaxf(m_0, mx0), mn1 = fmaxf(m_1, mx1);
        const float corr0 = __expf(m_0 - mn0), corr1 = __expf(m_1 - mn1);
        m_0 = mn0; m_1 = mn1;

        // P fragments in registers: A-frag order {r0c0, r1c0, r0c1, r1c1}
        uint32_t P[8][4];
        float rs0 = 0.f, rs1 = 0.f;
#pragma unroll
        for (int nt = 0; nt < 8; nt++) {
            const float p0 = __expf(S[nt][0] - mn0);   // r0 c0
            const float p1 = __expf(S[nt][1] - mn0);   // r0 c1
            const float p2 = __expf(S[nt][2] - mn1);   // r1 c0
            const float p3 = __expf(S[nt][3] - mn1);   // r1 c1
            rs0 += p0 + p1; rs1 += p2 + p3;
            P[nt][0] = f2tf(p0); P[nt][1] = f2tf(p2);
            P[nt][2] = f2tf(p1); P[nt][3] = f2tf(p3);
            O[nt][0] *= corr0; O[nt][1] *= corr0;
            O[nt][2] *= corr1; O[nt][3] *= corr1;
        }
        rs0 += __shfl_xor_sync(0xffffffffu, rs0, 1);
        rs0 += __shfl_xor_sync(0xffffffffu, rs0, 2);
        rs1 += __shfl_xor_sync(0xffffffffu, rs1, 1);
        rs1 += __shfl_xor_sync(0xffffffffu, rs1, 2);
        l_0 = l_0 * corr0 + rs0;
        l_1 = l_1 * corr1 + rs1;

        // ---- O += P V, low half (j-groups kg = 0..3; V rows kg*8+2qq,+1) ----
#pragma unroll
        for (int kg = 0; kg < 4; kg++) {
            const int jr = kg * 8 + 2 * qq;
#pragma unroll
            for (int nt = 0; nt < 8; nt++) {
                const int d = nt * 8 + qd;
                uint32_t bf[2];
                bf[0] = Vsu[jr * VS_STR + d];
                bf[1] = Vsu[(jr + 1) * VS_STR + d];
                mma_tf32(O[nt], P[kg], bf);
            }
        }

        // Vhigh(j) must be visible; Vlow(j) reads done -> refill low with j+1
        if (more) cp_wait1(); else cp_wait_all();
        bar_named(bar_id, 128);
        if (more) {
#pragma unroll
            for (int i = 0; i < 4; i++) {
                const int r = vr + 8 * i;
                cp16(VsA + (uint32_t)(r * VS_STR + vc) * 4,
                     &g_v[((size_t)(b * SEQ + j0 + 64 + r)) * DIM + h * HD + vc]);
            }
            cp_commit();     // group B'
        }

        // ---- O += P V, high half (kg = 4..7) ----
#pragma unroll
        for (int kg = 4; kg < 8; kg++) {
            const int jr = kg * 8 + 2 * qq;
#pragma unroll
            for (int nt = 0; nt < 8; nt++) {
                const int d = nt * 8 + qd;
                uint32_t bf[2];
                bf[0] = Vsu[jr * VS_STR + d];
                bf[1] = Vsu[(jr + 1) * VS_STR + d];
                mma_tf32(O[nt], P[kg], bf);
            }
        }

        bar_named(bar_id, 128);   // high reads done -> safe to refill high
        if (more) {
#pragma unroll
            for (int i = 0; i < 4; i++) {
                const int r = 32 + vr + 8 * i;
                cp16(VsA + (uint32_t)(r * VS_STR + vc) * 4,
                     &g_v[((size_t)(b * SEQ + j0 + 64 + r)) * DIM + h * HD + vc]);
            }
            cp_commit();     // group C'
        }
    }

    // Epilogue: normalize, write ctx (B,N,768) fp32
    const float inv0 = 1.f / l_0, inv1 = 1.f / l_1;
    const size_t r0off = ((size_t)(b * SEQ + i0 + row0)) * DIM + h * HD;
    const size_t r1off = ((size_t)(b * SEQ + i0 + row1)) * DIM + h * HD;
#pragma unroll
    for (int nt = 0; nt < 8; nt++) {
        const int col = nt * 8 + 2 * qq;
        float2 o0; o0.x = O[nt][0] * inv0; o0.y = O[nt][1] * inv0;
        float2 o1; o1.x = O[nt][2] * inv1; o1.y = O[nt][3] * inv1;
        *(float2*)&ctx[r0off + col] = o0;
        *(float2*)&ctx[r1off + col] = o1;
    }
}

// ---------------------------------------------------------------------------
// Launch
// ---------------------------------------------------------------------------
extern "C" void kernel_launch(void* const* d_in, const int* in_sizes, int n_in,
                              void* d_out, int out_size)
{
    const float* x      = (const float*)d_in[0];
    const float* w_qkv  = (const float*)d_in[1];
    const float* mixl   = (const float*)d_in[2];
    const float* w_v    = (const float*)d_in[3];
    const float* w_proj = (const float*)d_in[4];
    const float* b_proj = (const float*)d_in[5];
    float* out = (float*)d_out;

    float *qk, *v, *ctx, *gl;
    cudaGetSymbolAddress((void**)&qk,  g_qk);
    cudaGetSymbolAddress((void**)&v,   g_v);
    cudaGetSymbolAddress((void**)&ctx, g_ctx);
    cudaGetSymbolAddress((void**)&gl,  g_gl);

    const int attn_smem = (4 * SG_K + HPC * 64 * VS_STR) * (int)sizeof(float);
    cudaFuncSetAttribute(fish_mix_attn, cudaFuncAttributeMaxDynamicSharedMemorySize, attn_smem);

    // 1) qk = x @ w_qkv[0:512]^T  -> tf32 bits
    tf32_gemm_nt<512, true, false><<<dim3(4, 64), 256>>>(x, w_qkv, nullptr, qk);
    // 2) v = x @ w_v^T            -> tf32 bits
    tf32_gemm_nt<768, true, false><<<dim3(6, 64), 256>>>(x, w_v, nullptr, v);
    // A) global logits per (b, k-head): gl = q_k . k_k^T  (fp32 raw)
    gl_gemm<<<dim3(8, 8, BB * KG), 256>>>(qk, gl);
    // B) mix + softmax + AV, 2 heads/CTA, register-resident P, 2 CTAs/SM
    fish_mix_attn<<<dim3(SEQ / 64, NH / HPC, BB), HPC * 128, attn_smem>>>(mixl, gl, ctx);
    // 4) out = ctx @ w_proj^T + b_proj (fp32 out)
    tf32_gemm_nt<768, false, true><<<dim3(6, 64), 256>>>(ctx, w_proj, b_proj, out);
}